// round 9
// baseline (speedup 1.0000x reference)
#include <cuda_runtime.h>
#include <cuda_bf16.h>
#include <cstdint>

// ---------------------------------------------------------------------------
// Problem constants
// ---------------------------------------------------------------------------
#define NN 100000   // nodes
#define NE 800000   // edges
#define NBLK 98     // ceil(NN/1024) for scan

// ---------------------------------------------------------------------------
// Device-global scratch
// ---------------------------------------------------------------------------
__device__ int   g_cnt[NN];
__device__ int   g_fill[NN];
__device__ int   g_rowptr[NN + 1];
__device__ int   g_bsum[128];
__device__ int   g_csrsrc[NE];
__device__ float g_dinv[NN];
__device__ __align__(16) float g_bufA[(size_t)NN * 256];   // GEMM out / agg in
__device__ __align__(16) float g_bufB[(size_t)NN * 256];   // agg out / apply in
__device__ __align__(16) __nv_bfloat16 g_ah[(size_t)NN * 256];  // GEMM A hi
__device__ __align__(16) __nv_bfloat16 g_al[(size_t)NN * 256];  // GEMM A lo
__device__ float g_S[2];     // LN sum, sumsq

// Transposed ([n][k]) bf16 hi/lo weight images
__device__ __align__(16) __nv_bfloat16 g_w1h[256 * 256], g_w1l[256 * 256];
__device__ __align__(16) __nv_bfloat16 g_w2h[256 * 256], g_w2l[256 * 256];
__device__ __align__(16) __nv_bfloat16 g_w3h[256 * 256], g_w3l[256 * 256];
__device__ __align__(16) __nv_bfloat16 g_w4h[128 * 256], g_w4l[128 * 256];

static __device__ __forceinline__ uint32_t smem_to_u32(const void* p) {
    uint32_t a;
    asm("{ .reg .u64 t; cvta.to.shared.u64 t, %1; cvt.u32.u64 %0, t; }" : "=r"(a) : "l"(p));
    return a;
}

#define LDMX4(r0, r1, r2, r3, addr) \
    asm volatile("ldmatrix.sync.aligned.m8n8.x4.shared.b16 {%0,%1,%2,%3}, [%4];" \
                 : "=r"(r0), "=r"(r1), "=r"(r2), "=r"(r3) : "r"(addr))

#define MMA16816(d, a, b) \
    asm volatile("mma.sync.aligned.m16n8k16.row.col.f32.bf16.bf16.f32 " \
                 "{%0,%1,%2,%3}, {%4,%5,%6,%7}, {%8,%9}, {%0,%1,%2,%3};" \
                 : "+f"((d)[0]), "+f"((d)[1]), "+f"((d)[2]), "+f"((d)[3]) \
                 : "r"((a)[0]), "r"((a)[1]), "r"((a)[2]), "r"((a)[3]), \
                   "r"((b)[0]), "r"((b)[1]))

#define CP_ASYNC16(saddr, gptr) \
    asm volatile("cp.async.cg.shared.global [%0], [%1], 16;" :: "r"(saddr), "l"(gptr))
#define CP_COMMIT() asm volatile("cp.async.commit_group;")
#define CP_WAIT1()  asm volatile("cp.async.wait_group 1;")
#define CP_WAIT0()  asm volatile("cp.async.wait_group 0;")

static __device__ __forceinline__ uint32_t packbf2(float a, float b) {
    __nv_bfloat162 t = __floats2bfloat162_rn(a, b);
    return *reinterpret_cast<uint32_t*>(&t);
}

// split a float4 into bf16-hi (uint2) and bf16-lo (uint2)
static __device__ __forceinline__ void split4(float4 v, uint2& hv, uint2& lv) {
    __nv_bfloat16 h0 = __float2bfloat16_rn(v.x), h1 = __float2bfloat16_rn(v.y);
    __nv_bfloat16 h2 = __float2bfloat16_rn(v.z), h3 = __float2bfloat16_rn(v.w);
    float l0 = v.x - __bfloat162float(h0), l1 = v.y - __bfloat162float(h1);
    float l2 = v.z - __bfloat162float(h2), l3 = v.w - __bfloat162float(h3);
    __nv_bfloat162 hh01; hh01.x = h0; hh01.y = h1;
    __nv_bfloat162 hh23; hh23.x = h2; hh23.y = h3;
    hv = make_uint2(*reinterpret_cast<uint32_t*>(&hh01),
                    *reinterpret_cast<uint32_t*>(&hh23));
    lv = make_uint2(packbf2(l0, l1), packbf2(l2, l3));
}

// ---------------------------------------------------------------------------
// CSR build
// ---------------------------------------------------------------------------
__global__ void k_zero_counts() {
    int i = blockIdx.x * blockDim.x + threadIdx.x;
    if (i < NN) { g_cnt[i] = 0; g_fill[i] = 0; }
}
__global__ void k_degree(const int* __restrict__ dst) {
    int e = blockIdx.x * blockDim.x + threadIdx.x;
    if (e < NE) atomicAdd(&g_cnt[dst[e]], 1);
}
__global__ void k_dinv() {
    int v = blockIdx.x * blockDim.x + threadIdx.x;
    if (v < NN) g_dinv[v] = rsqrtf((float)g_cnt[v] + 1.0f);
}
__global__ void k_scan1() {
    __shared__ int s[1024];
    int t = threadIdx.x;
    int i = blockIdx.x * 1024 + t;
    int v = (i < NN) ? g_cnt[i] : 0;
    s[t] = v;
    __syncthreads();
    for (int off = 1; off < 1024; off <<= 1) {
        int add = (t >= off) ? s[t - off] : 0;
        __syncthreads();
        s[t] += add;
        __syncthreads();
    }
    if (i < NN) g_rowptr[i] = s[t] - v;
    if (t == 1023) g_bsum[blockIdx.x] = s[1023];
}
__global__ void k_scan2() {
    int run = 0;
    for (int b = 0; b < NBLK; b++) { int x = g_bsum[b]; g_bsum[b] = run; run += x; }
    g_rowptr[NN] = run;
}
__global__ void k_scan3() {
    int i = blockIdx.x * blockDim.x + threadIdx.x;
    if (i < NN) g_rowptr[i] += g_bsum[i >> 10];
}
__global__ void k_scatter(const int* __restrict__ src, const int* __restrict__ dst) {
    int e = blockIdx.x * blockDim.x + threadIdx.x;
    if (e < NE) {
        int d = dst[e];
        int pos = g_rowptr[d] + atomicAdd(&g_fill[d], 1);
        g_csrsrc[pos] = src[e];
    }
}

// ---------------------------------------------------------------------------
// Weight prep: W[k][n] fp32 -> transposed [n][k] bf16 hi/lo
// ---------------------------------------------------------------------------
__global__ void k_wprep(const float* __restrict__ W, __nv_bfloat16* __restrict__ hi,
                        __nv_bfloat16* __restrict__ lo, int Nc) {
    int i = blockIdx.x * blockDim.x + threadIdx.x;
    if (i >= 256 * Nc) return;
    int k = i / Nc, n = i - k * Nc;
    float w = W[i];
    __nv_bfloat16 h = __float2bfloat16_rn(w);
    float rem = w - __bfloat162float(h);
    __nv_bfloat16 l = __float2bfloat16_rn(rem);
    int o = n * 256 + k;
    hi[o] = h;
    lo[o] = l;
}

// X conversion (layer-1 input): fp32 -> bf16 hi/lo images
__global__ void k_xconv(const float* __restrict__ x,
                        __nv_bfloat16* __restrict__ ah, __nv_bfloat16* __restrict__ al) {
    int i4 = blockIdx.x * blockDim.x + threadIdx.x;  // NN*64 total
    float4 v = ((const float4*)x)[i4];
    uint2 hv, lv;
    split4(v, hv, lv);
    ((uint2*)ah)[i4] = hv;
    ((uint2*)al)[i4] = lv;
}

// ---------------------------------------------------------------------------
// bf16-split HMMA GEMM: C[M,NC] = A[M,256] @ W[256,NC]
// CTA 128x128, 8 warps (4m x 2n), warp tile 32x64, BK=32, 2-stage cp.async.
// Terms ah*wh + ah*wl + al*wh, fp32 accumulate.
// smem/stage: AH,AL 128x80B; WH,WL 128x80B = 40960 B. 2 stages = 80 KB.
// B fragments consumed in two n-halves to bound register pressure.
// ---------------------------------------------------------------------------
#define ST_AH 0
#define ST_AL 10240
#define ST_WH 20480
#define ST_WL 30720
#define STAGE_SZ 40960
#define GEMM_SMEM (2 * STAGE_SZ)   // 81920 >= 128*132*4 = 67584 epilogue

template <int NC>
__global__ void __launch_bounds__(256, 2)
k_gemm_mma(const __nv_bfloat16* __restrict__ Ah,
           const __nv_bfloat16* __restrict__ Al,
           const __nv_bfloat16* __restrict__ Whi,
           const __nv_bfloat16* __restrict__ Wlo,
           float* __restrict__ C, int M)
{
    extern __shared__ __align__(16) char smem[];
    uint32_t sb = smem_to_u32(smem);

    int tid = threadIdx.x;
    int wid = tid >> 5, lane = tid & 31;
    int m0 = blockIdx.y * 128;
    int bn = blockIdx.x * 128;
    int warp_m = wid & 3;        // rows warp_m*32
    int warp_n = wid >> 2;       // cols warp_n*64

    // zero LN stats for the aggregation kernel that follows this GEMM
    if (blockIdx.x == 0 && blockIdx.y == 0 && tid == 0) {
        g_S[0] = 0.f; g_S[1] = 0.f;
    }

    float acc[2][8][4];
#pragma unroll
    for (int i = 0; i < 2; i++)
#pragma unroll
        for (int j = 0; j < 8; j++)
#pragma unroll
            for (int q = 0; q < 4; q++) acc[i][j][q] = 0.f;

    // ---- copy mappings: 2 threads per 64B row (rows are 512B in gmem) ----
    int arow = tid >> 1, half = tid & 1;
    int gra = m0 + arow; if (gra > M - 1) gra = M - 1;   // clamp (rows unused)
    const char* gAh = (const char*)(Ah + (size_t)gra * 256) + half * 32;
    const char* gAl = (const char*)(Al + (size_t)gra * 256) + half * 32;
    uint32_t sAoff = (uint32_t)arow * 80u + (uint32_t)half * 32u;
    int wrow = arow;  // W tile also has 128 rows (bn..bn+127)
    const char* gWh = (const char*)(Whi + (size_t)(bn + wrow) * 256) + half * 32;
    const char* gWl = (const char*)(Wlo + (size_t)(bn + wrow) * 256) + half * 32;
    uint32_t sWoff = sAoff;

    // ---- ldmatrix per-thread relative offsets ----
    uint32_t aRel[2], lRel[2];
#pragma unroll
    for (int i = 0; i < 2; i++) {
        uint32_t row = warp_m * 32 + i * 16 + (lane & 15);
        uint32_t col = ((lane >> 4) & 1) * 16;
        aRel[i] = ST_AH + row * 80 + col;
        lRel[i] = ST_AL + row * 80 + col;
    }
    uint32_t bRel[4], blRel[4];
#pragma unroll
    for (int p = 0; p < 4; p++) {
        uint32_t row = warp_n * 64 + p * 16 + (lane & 7) + ((lane >> 4) & 1) * 8;
        uint32_t col = ((lane >> 3) & 1) * 16;
        bRel[p]  = ST_WH + row * 80 + col;
        blRel[p] = ST_WL + row * 80 + col;
    }

    auto issue = [&](int kc, int stg) {
        uint32_t base = sb + stg * STAGE_SZ;
        int gofs = kc * 64;
        CP_ASYNC16(base + ST_AH + sAoff,      gAh + gofs);
        CP_ASYNC16(base + ST_AH + sAoff + 16, gAh + gofs + 16);
        CP_ASYNC16(base + ST_AL + sAoff,      gAl + gofs);
        CP_ASYNC16(base + ST_AL + sAoff + 16, gAl + gofs + 16);
        CP_ASYNC16(base + ST_WH + sWoff,      gWh + gofs);
        CP_ASYNC16(base + ST_WH + sWoff + 16, gWh + gofs + 16);
        CP_ASYNC16(base + ST_WL + sWoff,      gWl + gofs);
        CP_ASYNC16(base + ST_WL + sWoff + 16, gWl + gofs + 16);
    };

    issue(0, 0);
    CP_COMMIT();

    for (int kc = 0; kc < 8; kc++) {
        int cur = kc & 1;
        if (kc < 7) {
            issue(kc + 1, cur ^ 1);
            CP_COMMIT();
            CP_WAIT1();
        } else {
            CP_WAIT0();
        }
        __syncthreads();

        uint32_t base = sb + cur * STAGE_SZ;
#pragma unroll
        for (int s = 0; s < 2; s++) {
            uint32_t ah[2][4], al[2][4];
#pragma unroll
            for (int i = 0; i < 2; i++) {
                LDMX4(ah[i][0], ah[i][1], ah[i][2], ah[i][3], base + aRel[i] + s * 32);
                LDMX4(al[i][0], al[i][1], al[i][2], al[i][3], base + lRel[i] + s * 32);
            }
            // two n-halves to bound live registers
#pragma unroll
            for (int ph = 0; ph < 2; ph++) {
                uint32_t wh[4][2], wl[4][2];
                LDMX4(wh[0][0], wh[0][1], wh[1][0], wh[1][1], base + bRel[2 * ph] + s * 32);
                LDMX4(wh[2][0], wh[2][1], wh[3][0], wh[3][1], base + bRel[2 * ph + 1] + s * 32);
                LDMX4(wl[0][0], wl[0][1], wl[1][0], wl[1][1], base + blRel[2 * ph] + s * 32);
                LDMX4(wl[2][0], wl[2][1], wl[3][0], wl[3][1], base + blRel[2 * ph + 1] + s * 32);
#pragma unroll
                for (int i = 0; i < 2; i++)
#pragma unroll
                    for (int j = 0; j < 4; j++) {
                        MMA16816(acc[i][ph * 4 + j], ah[i], wh[j]);
                        MMA16816(acc[i][ph * 4 + j], ah[i], wl[j]);
                        MMA16816(acc[i][ph * 4 + j], al[i], wh[j]);
                    }
            }
        }
        __syncthreads();
    }

    // ---- epilogue: stage 128x128 fp32 tile in smem (stride 132 floats) ----
    float* otile = (float*)smem;
#pragma unroll
    for (int i = 0; i < 2; i++)
#pragma unroll
        for (int j = 0; j < 8; j++) {
            int r0 = warp_m * 32 + i * 16 + (lane >> 2);
            int c0 = warp_n * 64 + j * 8 + (lane & 3) * 2;
            *(float2*)(otile + r0 * 132 + c0)       = make_float2(acc[i][j][0], acc[i][j][1]);
            *(float2*)(otile + (r0 + 8) * 132 + c0) = make_float2(acc[i][j][2], acc[i][j][3]);
        }
    __syncthreads();

#pragma unroll
    for (int it = 0; it < 16; it++) {
        int idx = tid + it * 256;     // 0..4095 float4 slots
        int row = idx >> 5;
        int c4 = idx & 31;
        int gr = m0 + row;
        if (gr < M) {
            float4 v = *(float4*)(otile + row * 132 + c4 * 4);
            *(float4*)(C + (size_t)gr * NC + bn + c4 * 4) = v;
        }
    }
}

// ---------------------------------------------------------------------------
// Aggregation: out[v] = dinv[v]*(sum dinv[src]*h[src] + dinv[v]*h[v]) + bias
// One warp/node; neighbor loop unrolled x4 for memory-level parallelism.
// ---------------------------------------------------------------------------
__global__ void k_agg256(const float* __restrict__ h, const float* __restrict__ bias,
                         float* __restrict__ out, int stats)
{
    int warp = threadIdx.x >> 5, lane = threadIdx.x & 31;
    int v = blockIdx.x * 8 + warp;

    float4 a0 = make_float4(0.f, 0.f, 0.f, 0.f);
    float4 a1 = make_float4(0.f, 0.f, 0.f, 0.f);

    int beg = g_rowptr[v], end = g_rowptr[v + 1];
    int nb = end - beg;
    for (int base = 0; base < nb; base += 32) {
        int rem = nb - base;
        int cnt = rem < 32 ? rem : 32;
        int idx = base + lane;
        int sl = (idx < nb) ? g_csrsrc[beg + idx] : 0;
        float wl = (idx < nb) ? g_dinv[sl] : 0.f;
        int j = 0;
        for (; j + 4 <= cnt; j += 4) {
            int   s0 = __shfl_sync(0xffffffffu, sl, j);
            int   s1 = __shfl_sync(0xffffffffu, sl, j + 1);
            int   s2 = __shfl_sync(0xffffffffu, sl, j + 2);
            int   s3 = __shfl_sync(0xffffffffu, sl, j + 3);
            float w0 = __shfl_sync(0xffffffffu, wl, j);
            float w1 = __shfl_sync(0xffffffffu, wl, j + 1);
            float w2 = __shfl_sync(0xffffffffu, wl, j + 2);
            float w3 = __shfl_sync(0xffffffffu, wl, j + 3);
            const float4* r0 = (const float4*)(h + (size_t)s0 * 256);
            const float4* r1 = (const float4*)(h + (size_t)s1 * 256);
            const float4* r2 = (const float4*)(h + (size_t)s2 * 256);
            const float4* r3 = (const float4*)(h + (size_t)s3 * 256);
            float4 p0a = r0[lane], p0b = r0[lane + 32];
            float4 p1a = r1[lane], p1b = r1[lane + 32];
            float4 p2a = r2[lane], p2b = r2[lane + 32];
            float4 p3a = r3[lane], p3b = r3[lane + 32];
            a0.x += w0 * p0a.x; a0.y += w0 * p0a.y; a0.z += w0 * p0a.z; a0.w += w0 * p0a.w;
            a1.x += w0 * p0b.x; a1.y += w0 * p0b.y; a1.z += w0 * p0b.z; a1.w += w0 * p0b.w;
            a0.x += w1 * p1a.x; a0.y += w1 * p1a.y; a0.z += w1 * p1a.z; a0.w += w1 * p1a.w;
            a1.x += w1 * p1b.x; a1.y += w1 * p1b.y; a1.z += w1 * p1b.z; a1.w += w1 * p1b.w;
            a0.x += w2 * p2a.x; a0.y += w2 * p2a.y; a0.z += w2 * p2a.z; a0.w += w2 * p2a.w;
            a1.x += w2 * p2b.x; a1.y += w2 * p2b.y; a1.z += w2 * p2b.z; a1.w += w2 * p2b.w;
            a0.x += w3 * p3a.x; a0.y += w3 * p3a.y; a0.z += w3 * p3a.z; a0.w += w3 * p3a.w;
            a1.x += w3 * p3b.x; a1.y += w3 * p3b.y; a1.z += w3 * p3b.z; a1.w += w3 * p3b.w;
        }
        for (; j < cnt; j++) {
            int   s = __shfl_sync(0xffffffffu, sl, j);
            float w = __shfl_sync(0xffffffffu, wl, j);
            const float4* rr = (const float4*)(h + (size_t)s * 256);
            float4 f0 = rr[lane], f1 = rr[lane + 32];
            a0.x += w * f0.x; a0.y += w * f0.y; a0.z += w * f0.z; a0.w += w * f0.w;
            a1.x += w * f1.x; a1.y += w * f1.y; a1.z += w * f1.z; a1.w += w * f1.w;
        }
    }
    float dv = g_dinv[v];
    {
        const float4* rr = (const float4*)(h + (size_t)v * 256);
        float4 f0 = rr[lane], f1 = rr[lane + 32];
        a0.x += dv * f0.x; a0.y += dv * f0.y; a0.z += dv * f0.z; a0.w += dv * f0.w;
        a1.x += dv * f1.x; a1.y += dv * f1.y; a1.z += dv * f1.z; a1.w += dv * f1.w;
    }
    const float4* bb = (const float4*)bias;
    float4 b0 = bb[lane], b1 = bb[lane + 32];
    float4 r0, r1;
    r0.x = a0.x * dv + b0.x; r0.y = a0.y * dv + b0.y;
    r0.z = a0.z * dv + b0.z; r0.w = a0.w * dv + b0.w;
    r1.x = a1.x * dv + b1.x; r1.y = a1.y * dv + b1.y;
    r1.z = a1.z * dv + b1.z; r1.w = a1.w * dv + b1.w;

    float4* op = (float4*)(out + (size_t)v * 256);
    op[lane] = r0; op[lane + 32] = r1;

    if (stats) {
        float lsum = r0.x + r0.y + r0.z + r0.w + r1.x + r1.y + r1.z + r1.w;
        float lsq  = r0.x*r0.x + r0.y*r0.y + r0.z*r0.z + r0.w*r0.w
                   + r1.x*r1.x + r1.y*r1.y + r1.z*r1.z + r1.w*r1.w;
#pragma unroll
        for (int off = 16; off > 0; off >>= 1) {
            lsum += __shfl_down_sync(0xffffffffu, lsum, off);
            lsq  += __shfl_down_sync(0xffffffffu, lsq,  off);
        }
        __shared__ float ss[8], sq[8];
        if (lane == 0) { ss[warp] = lsum; sq[warp] = lsq; }
        __syncthreads();
        if (threadIdx.x == 0) {
            float S = 0.f, Q = 0.f;
#pragma unroll
            for (int w = 0; w < 8; w++) { S += ss[w]; Q += sq[w]; }
            atomicAdd(&g_S[0], S);
            atomicAdd(&g_S[1], Q);
        }
    }
}

__global__ void k_agg128(const float* __restrict__ h, const float* __restrict__ bias,
                         float* __restrict__ out)
{
    int warp = threadIdx.x >> 5, lane = threadIdx.x & 31;
    int v = blockIdx.x * 8 + warp;

    float4 a0 = make_float4(0.f, 0.f, 0.f, 0.f);
    int beg = g_rowptr[v], end = g_rowptr[v + 1];
    int nb = end - beg;
    for (int base = 0; base < nb; base += 32) {
        int rem = nb - base;
        int cnt = rem < 32 ? rem : 32;
        int idx = base + lane;
        int sl = (idx < nb) ? g_csrsrc[beg + idx] : 0;
        float wl = (idx < nb) ? g_dinv[sl] : 0.f;
        int j = 0;
        for (; j + 4 <= cnt; j += 4) {
            int   s0 = __shfl_sync(0xffffffffu, sl, j);
            int   s1 = __shfl_sync(0xffffffffu, sl, j + 1);
            int   s2 = __shfl_sync(0xffffffffu, sl, j + 2);
            int   s3 = __shfl_sync(0xffffffffu, sl, j + 3);
            float w0 = __shfl_sync(0xffffffffu, wl, j);
            float w1 = __shfl_sync(0xffffffffu, wl, j + 1);
            float w2 = __shfl_sync(0xffffffffu, wl, j + 2);
            float w3 = __shfl_sync(0xffffffffu, wl, j + 3);
            float4 p0 = ((const float4*)(h + (size_t)s0 * 128))[lane];
            float4 p1 = ((const float4*)(h + (size_t)s1 * 128))[lane];
            float4 p2 = ((const float4*)(h + (size_t)s2 * 128))[lane];
            float4 p3 = ((const float4*)(h + (size_t)s3 * 128))[lane];
            a0.x += w0 * p0.x; a0.y += w0 * p0.y; a0.z += w0 * p0.z; a0.w += w0 * p0.w;
            a0.x += w1 * p1.x; a0.y += w1 * p1.y; a0.z += w1 * p1.z; a0.w += w1 * p1.w;
            a0.x += w2 * p2.x; a0.y += w2 * p2.y; a0.z += w2 * p2.z; a0.w += w2 * p2.w;
            a0.x += w3 * p3.x; a0.y += w3 * p3.y; a0.z += w3 * p3.z; a0.w += w3 * p3.w;
        }
        for (; j < cnt; j++) {
            int   s = __shfl_sync(0xffffffffu, sl, j);
            float w = __shfl_sync(0xffffffffu, wl, j);
            float4 f0 = ((const float4*)(h + (size_t)s * 128))[lane];
            a0.x += w * f0.x; a0.y += w * f0.y; a0.z += w * f0.z; a0.w += w * f0.w;
        }
    }
    float dv = g_dinv[v];
    {
        float4 f0 = ((const float4*)(h + (size_t)v * 128))[lane];
        a0.x += dv * f0.x; a0.y += dv * f0.y; a0.z += dv * f0.z; a0.w += dv * f0.w;
    }
    const float4* bb = (const float4*)bias;
    float4 b0 = bb[lane];
    float4 r0;
    r0.x = a0.x * dv + b0.x; r0.y = a0.y * dv + b0.y;
    r0.z = a0.z * dv + b0.z; r0.w = a0.w * dv + b0.w;
    ((float4*)(out + (size_t)v * 128))[lane] = r0;
}

// ---------------------------------------------------------------------------
// LayerNorm apply: derives mean/invstd inline from g_S,
// y = lrelu((x-mean)*invstd*gamma + beta), emitted as bf16 hi/lo for next GEMM
// ---------------------------------------------------------------------------
__global__ void k_apply(const float* __restrict__ buf,
                        const float* __restrict__ gma,
                        const float* __restrict__ bta,
                        __nv_bfloat16* __restrict__ ah,
                        __nv_bfloat16* __restrict__ al)
{
    const float cnt = (float)NN * 256.0f;
    float mean = g_S[0] / cnt;
    float var  = fmaxf(g_S[1] / cnt - mean * mean, 0.f);
    float scale = 1.0f / (sqrtf(var) + 1e-5f);

    int i4 = blockIdx.x * blockDim.x + threadIdx.x;  // NN*64 total
    int c4 = i4 & 63;
    float4 g = ((const float4*)gma)[c4];
    float4 b = ((const float4*)bta)[c4];
    float4 v = ((const float4*)buf)[i4];
    v.x = (v.x - mean) * scale * g.x + b.x;
    v.y = (v.y - mean) * scale * g.y + b.y;
    v.z = (v.z - mean) * scale * g.z + b.z;
    v.w = (v.w - mean) * scale * g.w + b.w;
    v.x = v.x > 0.f ? v.x : 0.01f * v.x;
    v.y = v.y > 0.f ? v.y : 0.01f * v.y;
    v.z = v.z > 0.f ? v.z : 0.01f * v.z;
    v.w = v.w > 0.f ? v.w : 0.01f * v.w;
    uint2 hv, lv;
    split4(v, hv, lv);
    ((uint2*)ah)[i4] = hv;
    ((uint2*)al)[i4] = lv;
}

// ---------------------------------------------------------------------------
// Host launcher
// ---------------------------------------------------------------------------
extern "C" void kernel_launch(void* const* d_in, const int* in_sizes, int n_in,
                              void* d_out, int out_size)
{
    const float* x   = (const float*)d_in[0];
    const int*   ei  = (const int*)d_in[1];
    const int*   src = ei;
    const int*   dst = ei + NE;
    const float* W1 = (const float*)d_in[2];
    const float* b1 = (const float*)d_in[3];
    const float* g1 = (const float*)d_in[4];
    const float* e1 = (const float*)d_in[5];
    const float* W2 = (const float*)d_in[6];
    const float* b2 = (const float*)d_in[7];
    const float* g2 = (const float*)d_in[8];
    const float* e2 = (const float*)d_in[9];
    const float* W3 = (const float*)d_in[10];
    const float* b3 = (const float*)d_in[11];
    const float* g3 = (const float*)d_in[12];
    const float* e3 = (const float*)d_in[13];
    const float* W4 = (const float*)d_in[14];
    const float* b4 = (const float*)d_in[15];
    float* out = (float*)d_out;

    float *bufA = nullptr, *bufB = nullptr;
    cudaGetSymbolAddress((void**)&bufA, g_bufA);
    cudaGetSymbolAddress((void**)&bufB, g_bufB);
    __nv_bfloat16 *ah, *al;
    cudaGetSymbolAddress((void**)&ah, g_ah);
    cudaGetSymbolAddress((void**)&al, g_al);
    __nv_bfloat16 *w1h, *w1l, *w2h, *w2l, *w3h, *w3l, *w4h, *w4l;
    cudaGetSymbolAddress((void**)&w1h, g_w1h); cudaGetSymbolAddress((void**)&w1l, g_w1l);
    cudaGetSymbolAddress((void**)&w2h, g_w2h); cudaGetSymbolAddress((void**)&w2l, g_w2l);
    cudaGetSymbolAddress((void**)&w3h, g_w3h); cudaGetSymbolAddress((void**)&w3l, g_w3l);
    cudaGetSymbolAddress((void**)&w4h, g_w4h); cudaGetSymbolAddress((void**)&w4l, g_w4l);

    static bool attr_done = false;
    if (!attr_done) {
        cudaFuncSetAttribute(k_gemm_mma<256>, cudaFuncAttributeMaxDynamicSharedMemorySize, GEMM_SMEM);
        cudaFuncSetAttribute(k_gemm_mma<128>, cudaFuncAttributeMaxDynamicSharedMemorySize, GEMM_SMEM);
        attr_done = true;
    }

    const int T = 256;
    dim3 grid256(2, (NN + 127) / 128);    // x = n-block (BN=128), y = m-block
    dim3 grid128(1, (NN + 127) / 128);
    int aggBlocks = NN / 8;               // 12500
    int vecBlocks = (NN * 64) / T;        // 25000

    // ---- prep first (no CSR dependency) so ncu -s window hits the GEMM ----
    k_wprep<<<(256 * 256 + T - 1) / T, T>>>(W1, w1h, w1l, 256);   // #0
    k_wprep<<<(256 * 256 + T - 1) / T, T>>>(W2, w2h, w2l, 256);   // #1
    k_wprep<<<(256 * 256 + T - 1) / T, T>>>(W3, w3h, w3l, 256);   // #2
    k_wprep<<<(256 * 128 + T - 1) / T, T>>>(W4, w4h, w4l, 128);   // #3
    k_xconv<<<vecBlocks, T>>>(x, ah, al);                         // #4

    // ---- layer-1 GEMM (#5 — ncu capture target) ----
    k_gemm_mma<256><<<grid256, 256, GEMM_SMEM>>>(ah, al, w1h, w1l, bufA, NN);

    // ---- CSR build (needed before first aggregation) ----
    k_zero_counts<<<(NN + T - 1) / T, T>>>();
    k_degree<<<(NE + T - 1) / T, T>>>(dst);
    k_dinv<<<(NN + T - 1) / T, T>>>();
    k_scan1<<<NBLK, 1024>>>();
    k_scan2<<<1, 1>>>();
    k_scan3<<<(NN + T - 1) / T, T>>>();
    k_scatter<<<(NE + T - 1) / T, T>>>(src, dst);

    // ---- layer 1 (rest) ----
    k_agg256<<<aggBlocks, 256>>>(bufA, b1, bufB, 1);
    k_apply<<<vecBlocks, T>>>(bufB, g1, e1, ah, al);

    // ---- layer 2 ----
    k_gemm_mma<256><<<grid256, 256, GEMM_SMEM>>>(ah, al, w2h, w2l, bufA, NN);
    k_agg256<<<aggBlocks, 256>>>(bufA, b2, bufB, 1);
    k_apply<<<vecBlocks, T>>>(bufB, g2, e2, ah, al);

    // ---- layer 3 ----
    k_gemm_mma<256><<<grid256, 256, GEMM_SMEM>>>(ah, al, w3h, w3l, bufA, NN);
    k_agg256<<<aggBlocks, 256>>>(bufA, b3, bufB, 1);
    k_apply<<<vecBlocks, T>>>(bufB, g3, e3, ah, al);

    // ---- layer 4 (D=128, no LN) ----
    k_gemm_mma<128><<<grid128, 256, GEMM_SMEM>>>(ah, al, w4h, w4l, bufA, NN);
    k_agg128<<<aggBlocks, 256>>>(bufA, b4, out);
}

// round 10
// speedup vs baseline: 1.4073x; 1.4073x over previous
#include <cuda_runtime.h>
#include <cuda_bf16.h>
#include <cstdint>

// ---------------------------------------------------------------------------
// Problem constants
// ---------------------------------------------------------------------------
#define NN 100000   // nodes
#define NE 800000   // edges
#define NBLK 98     // ceil(NN/1024) for scan

// ---------------------------------------------------------------------------
// Device-global scratch
// ---------------------------------------------------------------------------
__device__ int   g_cnt[NN];
__device__ int   g_fill[NN];
__device__ int   g_rowptr[NN + 1];
__device__ int   g_bsum[128];
__device__ int   g_csrsrc[NE];
__device__ float g_dinv[NN];
__device__ __align__(16) float g_bufA[(size_t)NN * 256];   // GEMM out / agg in
__device__ __align__(16) float g_bufB[(size_t)NN * 256];   // agg out / apply in
__device__ __align__(16) __nv_bfloat16 g_ah[(size_t)NN * 256];  // GEMM A hi
__device__ __align__(16) __nv_bfloat16 g_al[(size_t)NN * 256];  // GEMM A lo
__device__ float g_S[2];     // LN sum, sumsq

// Transposed ([n][k]) bf16 hi/lo weight images
__device__ __align__(16) __nv_bfloat16 g_w1h[256 * 256], g_w1l[256 * 256];
__device__ __align__(16) __nv_bfloat16 g_w2h[256 * 256], g_w2l[256 * 256];
__device__ __align__(16) __nv_bfloat16 g_w3h[256 * 256], g_w3l[256 * 256];
__device__ __align__(16) __nv_bfloat16 g_w4h[128 * 256], g_w4l[128 * 256];

static __device__ __forceinline__ uint32_t smem_to_u32(const void* p) {
    uint32_t a;
    asm("{ .reg .u64 t; cvta.to.shared.u64 t, %1; cvt.u32.u64 %0, t; }" : "=r"(a) : "l"(p));
    return a;
}

#define LDMX4(r0, r1, r2, r3, addr) \
    asm volatile("ldmatrix.sync.aligned.m8n8.x4.shared.b16 {%0,%1,%2,%3}, [%4];" \
                 : "=r"(r0), "=r"(r1), "=r"(r2), "=r"(r3) : "r"(addr))

#define MMA16816(d, a, b) \
    asm volatile("mma.sync.aligned.m16n8k16.row.col.f32.bf16.bf16.f32 " \
                 "{%0,%1,%2,%3}, {%4,%5,%6,%7}, {%8,%9}, {%0,%1,%2,%3};" \
                 : "+f"((d)[0]), "+f"((d)[1]), "+f"((d)[2]), "+f"((d)[3]) \
                 : "r"((a)[0]), "r"((a)[1]), "r"((a)[2]), "r"((a)[3]), \
                   "r"((b)[0]), "r"((b)[1]))

#define CP_ASYNC16(saddr, gptr) \
    asm volatile("cp.async.cg.shared.global [%0], [%1], 16;" :: "r"(saddr), "l"(gptr))
#define CP_COMMIT() asm volatile("cp.async.commit_group;")
#define CP_WAIT1()  asm volatile("cp.async.wait_group 1;")
#define CP_WAIT0()  asm volatile("cp.async.wait_group 0;")

static __device__ __forceinline__ uint32_t packbf2(float a, float b) {
    __nv_bfloat162 t = __floats2bfloat162_rn(a, b);
    return *reinterpret_cast<uint32_t*>(&t);
}

// split a float4 into bf16-hi (uint2) and bf16-lo (uint2)
static __device__ __forceinline__ void split4(float4 v, uint2& hv, uint2& lv) {
    __nv_bfloat16 h0 = __float2bfloat16_rn(v.x), h1 = __float2bfloat16_rn(v.y);
    __nv_bfloat16 h2 = __float2bfloat16_rn(v.z), h3 = __float2bfloat16_rn(v.w);
    float l0 = v.x - __bfloat162float(h0), l1 = v.y - __bfloat162float(h1);
    float l2 = v.z - __bfloat162float(h2), l3 = v.w - __bfloat162float(h3);
    __nv_bfloat162 hh01; hh01.x = h0; hh01.y = h1;
    __nv_bfloat162 hh23; hh23.x = h2; hh23.y = h3;
    hv = make_uint2(*reinterpret_cast<uint32_t*>(&hh01),
                    *reinterpret_cast<uint32_t*>(&hh23));
    lv = make_uint2(packbf2(l0, l1), packbf2(l2, l3));
}

// ---------------------------------------------------------------------------
// CSR build
// ---------------------------------------------------------------------------
__global__ void k_zero_counts() {
    int i = blockIdx.x * blockDim.x + threadIdx.x;
    if (i < NN) { g_cnt[i] = 0; g_fill[i] = 0; }
}
__global__ void k_degree(const int* __restrict__ dst) {
    int e = blockIdx.x * blockDim.x + threadIdx.x;
    if (e < NE) atomicAdd(&g_cnt[dst[e]], 1);
}
__global__ void k_dinv() {
    int v = blockIdx.x * blockDim.x + threadIdx.x;
    if (v < NN) g_dinv[v] = rsqrtf((float)g_cnt[v] + 1.0f);
}
__global__ void k_scan1() {
    __shared__ int s[1024];
    int t = threadIdx.x;
    int i = blockIdx.x * 1024 + t;
    int v = (i < NN) ? g_cnt[i] : 0;
    s[t] = v;
    __syncthreads();
    for (int off = 1; off < 1024; off <<= 1) {
        int add = (t >= off) ? s[t - off] : 0;
        __syncthreads();
        s[t] += add;
        __syncthreads();
    }
    if (i < NN) g_rowptr[i] = s[t] - v;
    if (t == 1023) g_bsum[blockIdx.x] = s[1023];
}
__global__ void k_scan2() {
    int run = 0;
    for (int b = 0; b < NBLK; b++) { int x = g_bsum[b]; g_bsum[b] = run; run += x; }
    g_rowptr[NN] = run;
}
__global__ void k_scan3() {
    int i = blockIdx.x * blockDim.x + threadIdx.x;
    if (i < NN) g_rowptr[i] += g_bsum[i >> 10];
}
__global__ void k_scatter(const int* __restrict__ src, const int* __restrict__ dst) {
    int e = blockIdx.x * blockDim.x + threadIdx.x;
    if (e < NE) {
        int d = dst[e];
        int pos = g_rowptr[d] + atomicAdd(&g_fill[d], 1);
        g_csrsrc[pos] = src[e];
    }
}

// ---------------------------------------------------------------------------
// Weight prep: W[k][n] fp32 -> transposed [n][k] bf16 hi/lo
// ---------------------------------------------------------------------------
__global__ void k_wprep(const float* __restrict__ W, __nv_bfloat16* __restrict__ hi,
                        __nv_bfloat16* __restrict__ lo, int Nc) {
    int i = blockIdx.x * blockDim.x + threadIdx.x;
    if (i >= 256 * Nc) return;
    int k = i / Nc, n = i - k * Nc;
    float w = W[i];
    __nv_bfloat16 h = __float2bfloat16_rn(w);
    float rem = w - __bfloat162float(h);
    __nv_bfloat16 l = __float2bfloat16_rn(rem);
    int o = n * 256 + k;
    hi[o] = h;
    lo[o] = l;
}

// X conversion (layer-1 input): fp32 -> bf16 hi/lo images
__global__ void k_xconv(const float* __restrict__ x,
                        __nv_bfloat16* __restrict__ ah, __nv_bfloat16* __restrict__ al) {
    int i4 = blockIdx.x * blockDim.x + threadIdx.x;  // NN*64 total
    float4 v = ((const float4*)x)[i4];
    uint2 hv, lv;
    split4(v, hv, lv);
    ((uint2*)ah)[i4] = hv;
    ((uint2*)al)[i4] = lv;
}

// ---------------------------------------------------------------------------
// bf16-split HMMA GEMM: C[M,NC] = A[M,256] @ W[256,NC]
// A pre-converted to bf16 hi/lo. CTA 128x64, 8 warps (4m x 2n), BK=32,
// 3-stage cp.async pipeline. Terms ah*wh + ah*wl + al*wh, fp32 accumulate.
// Also zeroes the LN stats accumulator (block 0,0) for the downstream agg.
// (Exact R8 configuration — best measured: 1032 us.)
// ---------------------------------------------------------------------------
#define ST_AH 0
#define ST_AL 10240
#define ST_WH 20480
#define ST_WL 25600
#define STAGE_SZ 30720
#define NSTG 3
#define GEMM_SMEM (NSTG * STAGE_SZ)   // 92160 >= 34816 output staging

template <int NC>
__global__ void __launch_bounds__(256, 2)
k_gemm_mma(const __nv_bfloat16* __restrict__ Ah,
           const __nv_bfloat16* __restrict__ Al,
           const __nv_bfloat16* __restrict__ Whi,
           const __nv_bfloat16* __restrict__ Wlo,
           float* __restrict__ C, int M)
{
    extern __shared__ __align__(16) char smem[];
    uint32_t sb = smem_to_u32(smem);

    int tid = threadIdx.x;
    int wid = tid >> 5, lane = tid & 31;
    int m0 = blockIdx.y * 128;
    int bn = blockIdx.x * 64;
    int warp_m = wid & 3;
    int warp_n = wid >> 2;

    // zero LN stats for the aggregation kernel that follows this GEMM
    if (blockIdx.x == 0 && blockIdx.y == 0 && tid == 0) {
        g_S[0] = 0.f; g_S[1] = 0.f;
    }

    float acc[2][4][4];
#pragma unroll
    for (int i = 0; i < 2; i++)
#pragma unroll
        for (int j = 0; j < 4; j++)
#pragma unroll
            for (int q = 0; q < 4; q++) acc[i][j][q] = 0.f;

    // ---- copy mappings ----
    int arow = tid >> 1, ahalf = tid & 1;
    int gra = m0 + arow; if (gra > M - 1) gra = M - 1;   // clamp (rows unused)
    const char* gAh = (const char*)(Ah + (size_t)gra * 256) + ahalf * 32;
    const char* gAl = (const char*)(Al + (size_t)gra * 256) + ahalf * 32;
    uint32_t sAoff = (uint32_t)arow * 80u + (uint32_t)ahalf * 32u;
    int wr = tid >> 2, ws = tid & 3;
    const char* gWh = (const char*)(Whi + (size_t)(bn + wr) * 256) + ws * 16;
    const char* gWl = (const char*)(Wlo + (size_t)(bn + wr) * 256) + ws * 16;
    uint32_t sWoff = (uint32_t)wr * 80u + (uint32_t)ws * 16u;

    // ---- ldmatrix per-thread relative offsets ----
    uint32_t aRel[2], lRel[2];
#pragma unroll
    for (int i = 0; i < 2; i++) {
        uint32_t row = warp_m * 32 + i * 16 + (lane & 15);
        uint32_t col = ((lane >> 4) & 1) * 16;
        aRel[i] = ST_AH + row * 80 + col;
        lRel[i] = ST_AL + row * 80 + col;
    }
    uint32_t bRel[2], blRel[2];
#pragma unroll
    for (int p = 0; p < 2; p++) {
        uint32_t row = warp_n * 32 + p * 16 + (lane & 7) + ((lane >> 4) & 1) * 8;
        uint32_t col = ((lane >> 3) & 1) * 16;
        bRel[p]  = ST_WH + row * 80 + col;
        blRel[p] = ST_WL + row * 80 + col;
    }

    auto issue = [&](int kc, int stg) {
        uint32_t base = sb + stg * STAGE_SZ;
        int gofs = kc * 64;
        CP_ASYNC16(base + ST_AH + sAoff,      gAh + gofs);
        CP_ASYNC16(base + ST_AH + sAoff + 16, gAh + gofs + 16);
        CP_ASYNC16(base + ST_AL + sAoff,      gAl + gofs);
        CP_ASYNC16(base + ST_AL + sAoff + 16, gAl + gofs + 16);
        CP_ASYNC16(base + ST_WH + sWoff,      gWh + gofs);
        CP_ASYNC16(base + ST_WL + sWoff,      gWl + gofs);
    };

    issue(0, 0); CP_COMMIT();
    issue(1, 1); CP_COMMIT();

    for (int kc = 0; kc < 8; kc++) {
        if (kc < 7) CP_WAIT1(); else CP_WAIT0();
        __syncthreads();
        // prefetch 2 chunks ahead into the stage freed last iteration
        if (kc < 6) {
            issue(kc + 2, (kc + 2) % NSTG);
            CP_COMMIT();
        }

        uint32_t base = sb + (kc % NSTG) * STAGE_SZ;
#pragma unroll
        for (int s = 0; s < 2; s++) {
            uint32_t ah[2][4], al[2][4];
            uint32_t wh[4][2], wl[4][2];
#pragma unroll
            for (int i = 0; i < 2; i++) {
                LDMX4(ah[i][0], ah[i][1], ah[i][2], ah[i][3], base + aRel[i] + s * 32);
                LDMX4(al[i][0], al[i][1], al[i][2], al[i][3], base + lRel[i] + s * 32);
            }
#pragma unroll
            for (int p = 0; p < 2; p++) {
                LDMX4(wh[2 * p][0], wh[2 * p][1], wh[2 * p + 1][0], wh[2 * p + 1][1],
                      base + bRel[p] + s * 32);
                LDMX4(wl[2 * p][0], wl[2 * p][1], wl[2 * p + 1][0], wl[2 * p + 1][1],
                      base + blRel[p] + s * 32);
            }
#pragma unroll
            for (int i = 0; i < 2; i++)
#pragma unroll
                for (int j = 0; j < 4; j++) {
                    MMA16816(acc[i][j], ah[i], wh[j]);
                    MMA16816(acc[i][j], ah[i], wl[j]);
                    MMA16816(acc[i][j], al[i], wh[j]);
                }
        }
    }
    __syncthreads();  // all compute done before reusing smem for epilogue

    // ---- epilogue: stage 128x64 fp32 tile in smem (stride 68 floats) ----
    float* otile = (float*)smem;
#pragma unroll
    for (int i = 0; i < 2; i++)
#pragma unroll
        for (int j = 0; j < 4; j++) {
            int r0 = warp_m * 32 + i * 16 + (lane >> 2);
            int c0 = warp_n * 32 + j * 8 + (lane & 3) * 2;
            *(float2*)(otile + r0 * 68 + c0)       = make_float2(acc[i][j][0], acc[i][j][1]);
            *(float2*)(otile + (r0 + 8) * 68 + c0) = make_float2(acc[i][j][2], acc[i][j][3]);
        }
    __syncthreads();

#pragma unroll
    for (int it = 0; it < 8; it++) {
        int idx = tid + it * 256;
        int row = idx >> 4;
        int c4 = idx & 15;
        int gr = m0 + row;
        if (gr < M) {
            float4 v = *(float4*)(otile + row * 68 + c4 * 4);
            *(float4*)(C + (size_t)gr * NC + bn + c4 * 4) = v;
        }
    }
}

// ---------------------------------------------------------------------------
// Aggregation: out[v] = dinv[v]*(sum dinv[src]*h[src] + dinv[v]*h[v]) + bias
// One warp/node; neighbor loop unrolled x4 for memory-level parallelism.
// ---------------------------------------------------------------------------
__global__ void k_agg256(const float* __restrict__ h, const float* __restrict__ bias,
                         float* __restrict__ out, int stats)
{
    int warp = threadIdx.x >> 5, lane = threadIdx.x & 31;
    int v = blockIdx.x * 8 + warp;

    float4 a0 = make_float4(0.f, 0.f, 0.f, 0.f);
    float4 a1 = make_float4(0.f, 0.f, 0.f, 0.f);

    int beg = g_rowptr[v], end = g_rowptr[v + 1];
    int nb = end - beg;
    for (int base = 0; base < nb; base += 32) {
        int rem = nb - base;
        int cnt = rem < 32 ? rem : 32;
        int idx = base + lane;
        int sl = (idx < nb) ? g_csrsrc[beg + idx] : 0;
        float wl = (idx < nb) ? g_dinv[sl] : 0.f;
        int j = 0;
        for (; j + 4 <= cnt; j += 4) {
            int   s0 = __shfl_sync(0xffffffffu, sl, j);
            int   s1 = __shfl_sync(0xffffffffu, sl, j + 1);
            int   s2 = __shfl_sync(0xffffffffu, sl, j + 2);
            int   s3 = __shfl_sync(0xffffffffu, sl, j + 3);
            float w0 = __shfl_sync(0xffffffffu, wl, j);
            float w1 = __shfl_sync(0xffffffffu, wl, j + 1);
            float w2 = __shfl_sync(0xffffffffu, wl, j + 2);
            float w3 = __shfl_sync(0xffffffffu, wl, j + 3);
            const float4* r0 = (const float4*)(h + (size_t)s0 * 256);
            const float4* r1 = (const float4*)(h + (size_t)s1 * 256);
            const float4* r2 = (const float4*)(h + (size_t)s2 * 256);
            const float4* r3 = (const float4*)(h + (size_t)s3 * 256);
            float4 p0a = r0[lane], p0b = r0[lane + 32];
            float4 p1a = r1[lane], p1b = r1[lane + 32];
            float4 p2a = r2[lane], p2b = r2[lane + 32];
            float4 p3a = r3[lane], p3b = r3[lane + 32];
            a0.x += w0 * p0a.x; a0.y += w0 * p0a.y; a0.z += w0 * p0a.z; a0.w += w0 * p0a.w;
            a1.x += w0 * p0b.x; a1.y += w0 * p0b.y; a1.z += w0 * p0b.z; a1.w += w0 * p0b.w;
            a0.x += w1 * p1a.x; a0.y += w1 * p1a.y; a0.z += w1 * p1a.z; a0.w += w1 * p1a.w;
            a1.x += w1 * p1b.x; a1.y += w1 * p1b.y; a1.z += w1 * p1b.z; a1.w += w1 * p1b.w;
            a0.x += w2 * p2a.x; a0.y += w2 * p2a.y; a0.z += w2 * p2a.z; a0.w += w2 * p2a.w;
            a1.x += w2 * p2b.x; a1.y += w2 * p2b.y; a1.z += w2 * p2b.z; a1.w += w2 * p2b.w;
            a0.x += w3 * p3a.x; a0.y += w3 * p3a.y; a0.z += w3 * p3a.z; a0.w += w3 * p3a.w;
            a1.x += w3 * p3b.x; a1.y += w3 * p3b.y; a1.z += w3 * p3b.z; a1.w += w3 * p3b.w;
        }
        for (; j < cnt; j++) {
            int   s = __shfl_sync(0xffffffffu, sl, j);
            float w = __shfl_sync(0xffffffffu, wl, j);
            const float4* rr = (const float4*)(h + (size_t)s * 256);
            float4 f0 = rr[lane], f1 = rr[lane + 32];
            a0.x += w * f0.x; a0.y += w * f0.y; a0.z += w * f0.z; a0.w += w * f0.w;
            a1.x += w * f1.x; a1.y += w * f1.y; a1.z += w * f1.z; a1.w += w * f1.w;
        }
    }
    float dv = g_dinv[v];
    {
        const float4* rr = (const float4*)(h + (size_t)v * 256);
        float4 f0 = rr[lane], f1 = rr[lane + 32];
        a0.x += dv * f0.x; a0.y += dv * f0.y; a0.z += dv * f0.z; a0.w += dv * f0.w;
        a1.x += dv * f1.x; a1.y += dv * f1.y; a1.z += dv * f1.z; a1.w += dv * f1.w;
    }
    const float4* bb = (const float4*)bias;
    float4 b0 = bb[lane], b1 = bb[lane + 32];
    float4 r0, r1;
    r0.x = a0.x * dv + b0.x; r0.y = a0.y * dv + b0.y;
    r0.z = a0.z * dv + b0.z; r0.w = a0.w * dv + b0.w;
    r1.x = a1.x * dv + b1.x; r1.y = a1.y * dv + b1.y;
    r1.z = a1.z * dv + b1.z; r1.w = a1.w * dv + b1.w;

    float4* op = (float4*)(out + (size_t)v * 256);
    op[lane] = r0; op[lane + 32] = r1;

    if (stats) {
        float lsum = r0.x + r0.y + r0.z + r0.w + r1.x + r1.y + r1.z + r1.w;
        float lsq  = r0.x*r0.x + r0.y*r0.y + r0.z*r0.z + r0.w*r0.w
                   + r1.x*r1.x + r1.y*r1.y + r1.z*r1.z + r1.w*r1.w;
#pragma unroll
        for (int off = 16; off > 0; off >>= 1) {
            lsum += __shfl_down_sync(0xffffffffu, lsum, off);
            lsq  += __shfl_down_sync(0xffffffffu, lsq,  off);
        }
        __shared__ float ss[8], sq[8];
        if (lane == 0) { ss[warp] = lsum; sq[warp] = lsq; }
        __syncthreads();
        if (threadIdx.x == 0) {
            float S = 0.f, Q = 0.f;
#pragma unroll
            for (int w = 0; w < 8; w++) { S += ss[w]; Q += sq[w]; }
            atomicAdd(&g_S[0], S);
            atomicAdd(&g_S[1], Q);
        }
    }
}

__global__ void k_agg128(const float* __restrict__ h, const float* __restrict__ bias,
                         float* __restrict__ out)
{
    int warp = threadIdx.x >> 5, lane = threadIdx.x & 31;
    int v = blockIdx.x * 8 + warp;

    float4 a0 = make_float4(0.f, 0.f, 0.f, 0.f);
    int beg = g_rowptr[v], end = g_rowptr[v + 1];
    int nb = end - beg;
    for (int base = 0; base < nb; base += 32) {
        int rem = nb - base;
        int cnt = rem < 32 ? rem : 32;
        int idx = base + lane;
        int sl = (idx < nb) ? g_csrsrc[beg + idx] : 0;
        float wl = (idx < nb) ? g_dinv[sl] : 0.f;
        int j = 0;
        for (; j + 4 <= cnt; j += 4) {
            int   s0 = __shfl_sync(0xffffffffu, sl, j);
            int   s1 = __shfl_sync(0xffffffffu, sl, j + 1);
            int   s2 = __shfl_sync(0xffffffffu, sl, j + 2);
            int   s3 = __shfl_sync(0xffffffffu, sl, j + 3);
            float w0 = __shfl_sync(0xffffffffu, wl, j);
            float w1 = __shfl_sync(0xffffffffu, wl, j + 1);
            float w2 = __shfl_sync(0xffffffffu, wl, j + 2);
            float w3 = __shfl_sync(0xffffffffu, wl, j + 3);
            float4 p0 = ((const float4*)(h + (size_t)s0 * 128))[lane];
            float4 p1 = ((const float4*)(h + (size_t)s1 * 128))[lane];
            float4 p2 = ((const float4*)(h + (size_t)s2 * 128))[lane];
            float4 p3 = ((const float4*)(h + (size_t)s3 * 128))[lane];
            a0.x += w0 * p0.x; a0.y += w0 * p0.y; a0.z += w0 * p0.z; a0.w += w0 * p0.w;
            a0.x += w1 * p1.x; a0.y += w1 * p1.y; a0.z += w1 * p1.z; a0.w += w1 * p1.w;
            a0.x += w2 * p2.x; a0.y += w2 * p2.y; a0.z += w2 * p2.z; a0.w += w2 * p2.w;
            a0.x += w3 * p3.x; a0.y += w3 * p3.y; a0.z += w3 * p3.z; a0.w += w3 * p3.w;
        }
        for (; j < cnt; j++) {
            int   s = __shfl_sync(0xffffffffu, sl, j);
            float w = __shfl_sync(0xffffffffu, wl, j);
            float4 f0 = ((const float4*)(h + (size_t)s * 128))[lane];
            a0.x += w * f0.x; a0.y += w * f0.y; a0.z += w * f0.z; a0.w += w * f0.w;
        }
    }
    float dv = g_dinv[v];
    {
        float4 f0 = ((const float4*)(h + (size_t)v * 128))[lane];
        a0.x += dv * f0.x; a0.y += dv * f0.y; a0.z += dv * f0.z; a0.w += dv * f0.w;
    }
    const float4* bb = (const float4*)bias;
    float4 b0 = bb[lane];
    float4 r0;
    r0.x = a0.x * dv + b0.x; r0.y = a0.y * dv + b0.y;
    r0.z = a0.z * dv + b0.z; r0.w = a0.w * dv + b0.w;
    ((float4*)(out + (size_t)v * 128))[lane] = r0;
}

// ---------------------------------------------------------------------------
// LayerNorm apply: derives mean/invstd inline from g_S,
// y = lrelu((x-mean)*invstd*gamma + beta), emitted as bf16 hi/lo for next GEMM
// ---------------------------------------------------------------------------
__global__ void k_apply(const float* __restrict__ buf,
                        const float* __restrict__ gma,
                        const float* __restrict__ bta,
                        __nv_bfloat16* __restrict__ ah,
                        __nv_bfloat16* __restrict__ al)
{
    const float cnt = (float)NN * 256.0f;
    float mean = g_S[0] / cnt;
    float var  = fmaxf(g_S[1] / cnt - mean * mean, 0.f);
    float scale = 1.0f / (sqrtf(var) + 1e-5f);

    int i4 = blockIdx.x * blockDim.x + threadIdx.x;  // NN*64 total
    int c4 = i4 & 63;
    float4 g = ((const float4*)gma)[c4];
    float4 b = ((const float4*)bta)[c4];
    float4 v = ((const float4*)buf)[i4];
    v.x = (v.x - mean) * scale * g.x + b.x;
    v.y = (v.y - mean) * scale * g.y + b.y;
    v.z = (v.z - mean) * scale * g.z + b.z;
    v.w = (v.w - mean) * scale * g.w + b.w;
    v.x = v.x > 0.f ? v.x : 0.01f * v.x;
    v.y = v.y > 0.f ? v.y : 0.01f * v.y;
    v.z = v.z > 0.f ? v.z : 0.01f * v.z;
    v.w = v.w > 0.f ? v.w : 0.01f * v.w;
    uint2 hv, lv;
    split4(v, hv, lv);
    ((uint2*)ah)[i4] = hv;
    ((uint2*)al)[i4] = lv;
}

// ---------------------------------------------------------------------------
// Host launcher
// ---------------------------------------------------------------------------
extern "C" void kernel_launch(void* const* d_in, const int* in_sizes, int n_in,
                              void* d_out, int out_size)
{
    const float* x   = (const float*)d_in[0];
    const int*   ei  = (const int*)d_in[1];
    const int*   src = ei;
    const int*   dst = ei + NE;
    const float* W1 = (const float*)d_in[2];
    const float* b1 = (const float*)d_in[3];
    const float* g1 = (const float*)d_in[4];
    const float* e1 = (const float*)d_in[5];
    const float* W2 = (const float*)d_in[6];
    const float* b2 = (const float*)d_in[7];
    const float* g2 = (const float*)d_in[8];
    const float* e2 = (const float*)d_in[9];
    const float* W3 = (const float*)d_in[10];
    const float* b3 = (const float*)d_in[11];
    const float* g3 = (const float*)d_in[12];
    const float* e3 = (const float*)d_in[13];
    const float* W4 = (const float*)d_in[14];
    const float* b4 = (const float*)d_in[15];
    float* out = (float*)d_out;

    float *bufA = nullptr, *bufB = nullptr;
    cudaGetSymbolAddress((void**)&bufA, g_bufA);
    cudaGetSymbolAddress((void**)&bufB, g_bufB);
    __nv_bfloat16 *ah, *al;
    cudaGetSymbolAddress((void**)&ah, g_ah);
    cudaGetSymbolAddress((void**)&al, g_al);
    __nv_bfloat16 *w1h, *w1l, *w2h, *w2l, *w3h, *w3l, *w4h, *w4l;
    cudaGetSymbolAddress((void**)&w1h, g_w1h); cudaGetSymbolAddress((void**)&w1l, g_w1l);
    cudaGetSymbolAddress((void**)&w2h, g_w2h); cudaGetSymbolAddress((void**)&w2l, g_w2l);
    cudaGetSymbolAddress((void**)&w3h, g_w3h); cudaGetSymbolAddress((void**)&w3l, g_w3l);
    cudaGetSymbolAddress((void**)&w4h, g_w4h); cudaGetSymbolAddress((void**)&w4l, g_w4l);

    static bool attr_done = false;
    if (!attr_done) {
        cudaFuncSetAttribute(k_gemm_mma<256>, cudaFuncAttributeMaxDynamicSharedMemorySize, GEMM_SMEM);
        cudaFuncSetAttribute(k_gemm_mma<128>, cudaFuncAttributeMaxDynamicSharedMemorySize, GEMM_SMEM);
        attr_done = true;
    }

    const int T = 256;
    dim3 grid256(4, (NN + 127) / 128);    // x = n-block (BN=64), y = m-block
    dim3 grid128(2, (NN + 127) / 128);
    int aggBlocks = NN / 8;               // 12500
    int vecBlocks = (NN * 64) / T;        // 25000

    // ---- prep ordered so the layer-1 GEMM lands at launch index 3
    //      (empirically the launch ncu captures) ----
    k_wprep<<<(256 * 256 + T - 1) / T, T>>>(W1, w1h, w1l, 256);   // #0
    k_xconv<<<vecBlocks, T>>>(x, ah, al);                         // #1
    k_wprep<<<(256 * 256 + T - 1) / T, T>>>(W2, w2h, w2l, 256);   // #2
    // ---- layer-1 GEMM (#3 — ncu capture target) ----
    k_gemm_mma<256><<<grid256, 256, GEMM_SMEM>>>(ah, al, w1h, w1l, bufA, NN);
    k_wprep<<<(256 * 256 + T - 1) / T, T>>>(W3, w3h, w3l, 256);   // #4
    k_wprep<<<(256 * 128 + T - 1) / T, T>>>(W4, w4h, w4l, 128);   // #5

    // ---- CSR build (needed before first aggregation) ----
    k_zero_counts<<<(NN + T - 1) / T, T>>>();
    k_degree<<<(NE + T - 1) / T, T>>>(dst);
    k_dinv<<<(NN + T - 1) / T, T>>>();
    k_scan1<<<NBLK, 1024>>>();
    k_scan2<<<1, 1>>>();
    k_scan3<<<(NN + T - 1) / T, T>>>();
    k_scatter<<<(NE + T - 1) / T, T>>>(src, dst);

    // ---- layer 1 (rest) ----
    k_agg256<<<aggBlocks, 256>>>(bufA, b1, bufB, 1);
    k_apply<<<vecBlocks, T>>>(bufB, g1, e1, ah, al);

    // ---- layer 2 ----
    k_gemm_mma<256><<<grid256, 256, GEMM_SMEM>>>(ah, al, w2h, w2l, bufA, NN);
    k_agg256<<<aggBlocks, 256>>>(bufA, b2, bufB, 1);
    k_apply<<<vecBlocks, T>>>(bufB, g2, e2, ah, al);

    // ---- layer 3 ----
    k_gemm_mma<256><<<grid256, 256, GEMM_SMEM>>>(ah, al, w3h, w3l, bufA, NN);
    k_agg256<<<aggBlocks, 256>>>(bufA, b3, bufB, 1);
    k_apply<<<vecBlocks, T>>>(bufB, g3, e3, ah, al);

    // ---- layer 4 (D=128, no LN) ----
    k_gemm_mma<128><<<grid128, 256, GEMM_SMEM>>>(ah, al, w4h, w4l, bufA, NN);
    k_agg128<<<aggBlocks, 256>>>(bufA, b4, out);
}